// round 1
// baseline (speedup 1.0000x reference)
#include <cuda_runtime.h>
#include <math.h>

#define BB 16
#define CC 128
#define TT 16384
#define KSPLIT 8
#define KRANGE (TT / KSPLIT)   // 2048
#define KT 32
#define NKT (KRANGE / KT)      // 64
#define NG 3
#define NJOBS (BB * NG * KSPLIT)  // 384
#define PAD 4
#define CCP (CC + PAD)         // 132 floats -> 528B row stride, 16B aligned

// Scratch (no allocations allowed -> device globals)
__device__ float g_inv[2 * BB * CC];                       // [0..2047]=inv_s, [2048..4095]=inv_t
__device__ float g_gram[(size_t)KSPLIT * BB * NG * CC * CC];  // 25.2 MB partial grams
__device__ float g_bsum[BB * NG];                          // per-(b,g) weighted sums

// ---------------------------------------------------------------------------
// Kernel 1: inverse L2 norms of each (b,c) row of length T
// ---------------------------------------------------------------------------
__global__ void norm_kernel(const float* __restrict__ fs,
                            const float* __restrict__ ft) {
    int row = blockIdx.x;                    // 0..4095
    const float* src = (row < BB * CC) ? fs : ft;
    int r = (row < BB * CC) ? row : row - BB * CC;
    const float4* p = (const float4*)(src + (size_t)r * TT);

    float ss = 0.f;
    for (int i = threadIdx.x; i < TT / 4; i += blockDim.x) {
        float4 v = p[i];
        ss += v.x * v.x + v.y * v.y + v.z * v.z + v.w * v.w;
    }
    __shared__ float red[256];
    red[threadIdx.x] = ss;
    __syncthreads();
    for (int s = 128; s > 0; s >>= 1) {
        if (threadIdx.x < s) red[threadIdx.x] += red[threadIdx.x + s];
        __syncthreads();
    }
    if (threadIdx.x == 0) {
        float n = sqrtf(red[0]);
        g_inv[row] = 1.f / fmaxf(n, 1e-12f);
    }
}

// ---------------------------------------------------------------------------
// Kernel 2: partial Gram GEMM. One block = one (b, gram, k-split) job.
// Tile: full 128x128 output, K range 2048 in steps of 32.
// 256 threads, 8x8 micro-tile per thread.
// ---------------------------------------------------------------------------
__global__ __launch_bounds__(256, 2)
void gram_kernel(const float* __restrict__ fs,
                 const float* __restrict__ ft) {
    int bx  = blockIdx.x;
    int b   = bx / (NG * KSPLIT);
    int rem = bx % (NG * KSPLIT);
    int g   = rem / KSPLIT;
    int ks  = rem % KSPLIT;

    // g=0: tt, g=1: ss, g=2: st
    const float* A  = (g == 0) ? ft : fs;
    const float* Bm = (g == 1) ? fs : ft;
    const float* Ab = A  + (size_t)b * CC * TT;
    const float* Bb = Bm + (size_t)b * CC * TT;

    __shared__ float As[KT][CCP];   // transposed: As[k][row]
    __shared__ float Bs[KT][CCP];

    int tid  = threadIdx.x;
    int tx   = tid & 15;
    int ty   = tid >> 4;
    int lrow = tid >> 3;    // 0..31 loader row-within-group
    int lq   = tid & 7;     // 0..7 float4 quad along K

    float acc[8][8];
#pragma unroll
    for (int i = 0; i < 8; i++)
#pragma unroll
        for (int j = 0; j < 8; j++) acc[i][j] = 0.f;

    int k0 = ks * KRANGE;
    for (int kt = 0; kt < NKT; kt++, k0 += KT) {
        // Load 128 rows x 32 k of A and B, transposed into smem.
#pragma unroll
        for (int rg = 0; rg < 4; rg++) {
            int row = rg * 32 + lrow;
            float4 va = *(const float4*)(Ab + (size_t)row * TT + k0 + lq * 4);
            float4 vb = *(const float4*)(Bb + (size_t)row * TT + k0 + lq * 4);
            As[lq * 4 + 0][row] = va.x;
            As[lq * 4 + 1][row] = va.y;
            As[lq * 4 + 2][row] = va.z;
            As[lq * 4 + 3][row] = va.w;
            Bs[lq * 4 + 0][row] = vb.x;
            Bs[lq * 4 + 1][row] = vb.y;
            Bs[lq * 4 + 2][row] = vb.z;
            Bs[lq * 4 + 3][row] = vb.w;
        }
        __syncthreads();

#pragma unroll 4
        for (int k = 0; k < KT; k++) {
            const float4* a4 = (const float4*)&As[k][0];
            const float4* b4 = (const float4*)&Bs[k][0];
            float4 a0 = a4[ty * 2], a1 = a4[ty * 2 + 1];
            float4 b0 = b4[tx * 2], b1 = b4[tx * 2 + 1];
            float ar[8] = {a0.x, a0.y, a0.z, a0.w, a1.x, a1.y, a1.z, a1.w};
            float br[8] = {b0.x, b0.y, b0.z, b0.w, b1.x, b1.y, b1.z, b1.w};
#pragma unroll
            for (int i = 0; i < 8; i++)
#pragma unroll
                for (int j = 0; j < 8; j++)
                    acc[i][j] += ar[i] * br[j];
        }
        __syncthreads();
    }

    float* out = g_gram + (((size_t)ks * BB + b) * NG + g) * (CC * CC);
#pragma unroll
    for (int i = 0; i < 8; i++) {
        int r = ty * 8 + i;
#pragma unroll
        for (int j = 0; j < 8; j++)
            out[r * CC + tx * 8 + j] = acc[i][j];
    }
}

// ---------------------------------------------------------------------------
// Kernel 3: reduce K-split partials, scale by inverse norms, square, weight.
// One block per (b, g). Deterministic (no float atomics).
// ---------------------------------------------------------------------------
__global__ void reduce_kernel() {
    int bx = blockIdx.x;     // 0..47
    int b  = bx / NG;
    int g  = bx % NG;

    const float* inv_s = g_inv;
    const float* inv_t = g_inv + BB * CC;
    const float* invA = (g == 0) ? inv_t : inv_s;
    const float* invB = (g == 1) ? inv_s : inv_t;
    float w = (g == 2) ? -2.f : 1.f;

    const float* base = g_gram + ((size_t)b * NG + g) * (CC * CC);
    const size_t stride = (size_t)BB * NG * CC * CC;

    float lsum = 0.f;
    for (int e = threadIdx.x; e < CC * CC; e += blockDim.x) {
        float v = 0.f;
#pragma unroll
        for (int ks = 0; ks < KSPLIT; ks++) v += base[(size_t)ks * stride + e];
        int i = e >> 7;
        int j = e & 127;
        float gv = v * invA[b * CC + i] * invB[b * CC + j];
        lsum += gv * gv;
    }
    __shared__ float red[256];
    red[threadIdx.x] = lsum;
    __syncthreads();
    for (int s = 128; s > 0; s >>= 1) {
        if (threadIdx.x < s) red[threadIdx.x] += red[threadIdx.x + s];
        __syncthreads();
    }
    if (threadIdx.x == 0) g_bsum[bx] = w * red[0];
}

// ---------------------------------------------------------------------------
// Kernel 4: final scalar
// ---------------------------------------------------------------------------
__global__ void final_kernel(float* __restrict__ out) {
    __shared__ float red[64];
    float s = (threadIdx.x < BB * NG) ? g_bsum[threadIdx.x] : 0.f;
    red[threadIdx.x] = s;
    __syncthreads();
    for (int st = 32; st > 0; st >>= 1) {
        if (threadIdx.x < st) red[threadIdx.x] += red[threadIdx.x + st];
        __syncthreads();
    }
    if (threadIdx.x == 0)
        out[0] = red[0] / (float)(BB * CC * CC);
}

extern "C" void kernel_launch(void* const* d_in, const int* in_sizes, int n_in,
                              void* d_out, int out_size) {
    const float* fs = (const float*)d_in[0];
    const float* ft = (const float*)d_in[1];
    float* out = (float*)d_out;
    (void)in_sizes; (void)n_in; (void)out_size;

    norm_kernel<<<2 * BB * CC, 256>>>(fs, ft);
    gram_kernel<<<NJOBS, 256>>>(fs, ft);
    reduce_kernel<<<BB * NG, 256>>>();
    final_kernel<<<1, 64>>>(out);
}

// round 3
// speedup vs baseline: 2.5608x; 2.5608x over previous
#include <cuda_runtime.h>
#include <cuda_bf16.h>
#include <cstdint>
#include <math.h>

#define BB 16
#define CC 128
#define TT 16384
#define KSPLIT 16
#define KRANGE (TT / KSPLIT)      // 1024 floats per CTA K-range
#define KT 64                     // K per smem tile (64 bf16 = 128B rows)
#define NKT (KRANGE / KT)         // 16 tiles
#define NG 3
#define NJOBS (BB * NG * KSPLIT)  // 768 CTAs

#define TILE_BYTES 16384          // 128 rows x 64 bf16
#define STAGE_BYTES 32768         // A + B tile
#define DYN_SMEM 65536            // 2 stages

// Scratch (no device allocations allowed -> globals)
__device__ float g_gram[(size_t)KSPLIT * BB * NG * CC * CC];   // 50 MB partials
__device__ float g_bsum[BB * NG];

__device__ __forceinline__ uint32_t smem_u32(const void* p) {
    return (uint32_t)__cvta_generic_to_shared(p);
}
__device__ __forceinline__ uint32_t swz(uint32_t off) {
    return off ^ ((off >> 3) & 0x70);   // SW128: bits[9:7] ^-> bits[6:4]
}
__device__ __forceinline__ void ldsm4(uint32_t& r0, uint32_t& r1, uint32_t& r2,
                                      uint32_t& r3, uint32_t addr) {
    asm volatile("ldmatrix.sync.aligned.m8n8.x4.shared.b16 {%0,%1,%2,%3}, [%4];"
                 : "=r"(r0), "=r"(r1), "=r"(r2), "=r"(r3) : "r"(addr));
}
__device__ __forceinline__ void mma16816(float* c, const uint32_t* a,
                                         uint32_t b0, uint32_t b1) {
    asm volatile(
        "mma.sync.aligned.m16n8k16.row.col.f32.bf16.bf16.f32 "
        "{%0,%1,%2,%3}, {%4,%5,%6,%7}, {%8,%9}, {%0,%1,%2,%3};"
        : "+f"(c[0]), "+f"(c[1]), "+f"(c[2]), "+f"(c[3])
        : "r"(a[0]), "r"(a[1]), "r"(a[2]), "r"(a[3]), "r"(b0), "r"(b1));
}

// ---------------------------------------------------------------------------
// Gram kernel: one CTA per (b, gram, ksplit). 256 threads = 8 warps.
// Output 128x128 fp32 partial gram over K range of 1024.
// Warp tile 32x64 (wm=wid&3, wn=wid>>2): 2 m-tiles x 8 n-tiles of m16n8k16.
// ---------------------------------------------------------------------------
extern "C" __global__ void __launch_bounds__(256)
gram_kernel(const float* __restrict__ fs, const float* __restrict__ ft) {
    extern __shared__ char smem[];
    const uint32_t smb = smem_u32(smem);

    int bx  = blockIdx.x;
    int b   = bx / (NG * KSPLIT);
    int rem = bx % (NG * KSPLIT);
    int g   = rem / KSPLIT;
    int ks  = rem % KSPLIT;
    bool dual = (g == 2);

    const float* Am = (g == 0) ? ft : fs;
    const float* Bm = (g == 1) ? fs : ft;

    int tid  = threadIdx.x;
    int wid  = tid >> 5;
    int lane = tid & 31;
    int wm   = wid & 3;       // m block: 32*wm
    int wn   = wid >> 2;      // n block: 64*wn
    int gid  = lane >> 2;
    int tid4 = lane & 3;

    // Loader mapping: 2 threads per row, each covers 32 floats.
    int lr = tid >> 1;
    int lh = tid & 1;
    const float* rowA = Am + (size_t)b * CC * TT + (size_t)lr * TT + ks * KRANGE + lh * 32;
    const float* rowB = Bm + (size_t)b * CC * TT + (size_t)lr * TT + ks * KRANGE + lh * 32;
    uint32_t sts_off = (uint32_t)lr * 128 + (uint32_t)lh * 64;

    // ldmatrix lane addresses (byte offsets within a tile)
    uint32_t a_row  = (uint32_t)(wm * 32 + (lane & 15));
    uint32_t a_koff = (uint32_t)((lane >> 4) * 16);
    uint32_t b_rowbase = (uint32_t)(wn * 64 + ((lane >> 4) << 3) + (lane & 7));
    uint32_t b_koff = (uint32_t)(((lane >> 3) & 1) * 16);

    float acc[2][8][4];
#pragma unroll
    for (int mi = 0; mi < 2; mi++)
#pragma unroll
        for (int ni = 0; ni < 8; ni++)
#pragma unroll
            for (int q = 0; q < 4; q++) acc[mi][ni][q] = 0.f;

    // ---- prologue: tile 0 ----
    {
        uint2 sa[8], sb[8];
#pragma unroll
        for (int q = 0; q < 8; q++) {
            float4 v = ((const float4*)rowA)[q];
            __nv_bfloat162 lo = __floats2bfloat162_rn(v.x, v.y);
            __nv_bfloat162 hi = __floats2bfloat162_rn(v.z, v.w);
            sa[q] = make_uint2(*(uint32_t*)&lo, *(uint32_t*)&hi);
        }
        if (dual) {
#pragma unroll
            for (int q = 0; q < 8; q++) {
                float4 v = ((const float4*)rowB)[q];
                __nv_bfloat162 lo = __floats2bfloat162_rn(v.x, v.y);
                __nv_bfloat162 hi = __floats2bfloat162_rn(v.z, v.w);
                sb[q] = make_uint2(*(uint32_t*)&lo, *(uint32_t*)&hi);
            }
        }
#pragma unroll
        for (int q = 0; q < 8; q++)
            *(uint2*)(smem + swz(sts_off + q * 8)) = sa[q];
        if (dual) {
#pragma unroll
            for (int q = 0; q < 8; q++)
                *(uint2*)(smem + TILE_BYTES + swz(sts_off + q * 8)) = sb[q];
        }
    }
    __syncthreads();

    for (int kt = 0; kt < NKT; kt++) {
        int cur = kt & 1;
        int nxt = cur ^ 1;

        // prefetch next tile into registers (overlaps compute below)
        uint2 sa[8], sb[8];
        if (kt + 1 < NKT) {
            const float* pA = rowA + (kt + 1) * KT;
#pragma unroll
            for (int q = 0; q < 8; q++) {
                float4 v = ((const float4*)pA)[q];
                __nv_bfloat162 lo = __floats2bfloat162_rn(v.x, v.y);
                __nv_bfloat162 hi = __floats2bfloat162_rn(v.z, v.w);
                sa[q] = make_uint2(*(uint32_t*)&lo, *(uint32_t*)&hi);
            }
            if (dual) {
                const float* pB = rowB + (kt + 1) * KT;
#pragma unroll
                for (int q = 0; q < 8; q++) {
                    float4 v = ((const float4*)pB)[q];
                    __nv_bfloat162 lo = __floats2bfloat162_rn(v.x, v.y);
                    __nv_bfloat162 hi = __floats2bfloat162_rn(v.z, v.w);
                    sb[q] = make_uint2(*(uint32_t*)&lo, *(uint32_t*)&hi);
                }
            }
        }

        // compute 4 k16 steps from buffer cur
        uint32_t abase = smb + cur * STAGE_BYTES;
        uint32_t bbase = abase + (dual ? TILE_BYTES : 0);
#pragma unroll
        for (int kc = 0; kc < 4; kc++) {
            uint32_t kb = (uint32_t)(kc * 32);
            uint32_t afr[2][4];
#pragma unroll
            for (int mi = 0; mi < 2; mi++) {
                uint32_t addr = abase + swz((a_row + mi * 16) * 128 + kb + a_koff);
                ldsm4(afr[mi][0], afr[mi][1], afr[mi][2], afr[mi][3], addr);
            }
#pragma unroll
            for (int nb = 0; nb < 4; nb++) {
                uint32_t r0, r1, r2, r3;
                uint32_t addr = bbase + swz((b_rowbase + nb * 16) * 128 + kb + b_koff);
                ldsm4(r0, r1, r2, r3, addr);
                mma16816(acc[0][2 * nb],     afr[0], r0, r1);
                mma16816(acc[0][2 * nb + 1], afr[0], r2, r3);
                mma16816(acc[1][2 * nb],     afr[1], r0, r1);
                mma16816(acc[1][2 * nb + 1], afr[1], r2, r3);
            }
        }

        // store next tile
        if (kt + 1 < NKT) {
            char* sdst = smem + nxt * STAGE_BYTES;
#pragma unroll
            for (int q = 0; q < 8; q++)
                *(uint2*)(sdst + swz(sts_off + q * 8)) = sa[q];
            if (dual) {
#pragma unroll
                for (int q = 0; q < 8; q++)
                    *(uint2*)(sdst + TILE_BYTES + swz(sts_off + q * 8)) = sb[q];
            }
        }
        __syncthreads();
    }

    // ---- epilogue: write partial gram [i*CC + j], i = A row, j = B col ----
    float* out = g_gram + (((size_t)ks * BB + b) * NG + g) * (CC * CC);
#pragma unroll
    for (int mi = 0; mi < 2; mi++) {
        int r0 = wm * 32 + mi * 16 + gid;
#pragma unroll
        for (int ni = 0; ni < 8; ni++) {
            int c0 = wn * 64 + ni * 8 + tid4 * 2;
            *(float2*)(out + (size_t)r0 * CC + c0) =
                make_float2(acc[mi][ni][0], acc[mi][ni][1]);
            *(float2*)(out + (size_t)(r0 + 8) * CC + c0) =
                make_float2(acc[mi][ni][2], acc[mi][ni][3]);
        }
    }
}

// ---------------------------------------------------------------------------
// Reduce: sum K-split partials; inverse norms from full-K ss/tt diagonals;
// normalize, square, weight. One block per (b, g). Deterministic.
// ---------------------------------------------------------------------------
__global__ void reduce_kernel() {
    int bx = blockIdx.x;      // 0..47
    int b  = bx / NG;
    int g  = bx % NG;
    int tid = threadIdx.x;

    const size_t STRIDE = (size_t)BB * NG * CC * CC;
    __shared__ float inv_s[CC], inv_t[CC];

    if (tid < CC) {
        const float* base = g_gram + ((size_t)b * NG + 1) * (CC * CC) + (size_t)tid * (CC + 1);
        float v = 0.f;
#pragma unroll
        for (int ks = 0; ks < KSPLIT; ks++) v += base[ks * STRIDE];
        inv_s[tid] = rsqrtf(fmaxf(v, 1e-24f));
    } else if (tid < 2 * CC) {
        int d = tid - CC;
        const float* base = g_gram + ((size_t)b * NG + 0) * (CC * CC) + (size_t)d * (CC + 1);
        float v = 0.f;
#pragma unroll
        for (int ks = 0; ks < KSPLIT; ks++) v += base[ks * STRIDE];
        inv_t[d] = rsqrtf(fmaxf(v, 1e-24f));
    }
    __syncthreads();

    // element e at [i*CC + j]: i = A-side row, j = B-side col
    const float* iA = (g == 0) ? inv_t : inv_s;
    const float* iB = (g == 1) ? inv_s : inv_t;
    float w = (g == 2) ? -2.f : 1.f;
    const float* gb = g_gram + ((size_t)b * NG + g) * (CC * CC);

    float lsum = 0.f;
    for (int e4 = tid; e4 < CC * CC / 4; e4 += 256) {
        float4 v = make_float4(0.f, 0.f, 0.f, 0.f);
#pragma unroll
        for (int ks = 0; ks < KSPLIT; ks++) {
            float4 u = ((const float4*)(gb + ks * STRIDE))[e4];
            v.x += u.x; v.y += u.y; v.z += u.z; v.w += u.w;
        }
        int e = e4 * 4;
        int i = e >> 7;
        int j = e & 127;
        float ai = iA[i];
        float a0 = v.x * ai * iB[j];
        float a1 = v.y * ai * iB[j + 1];
        float a2 = v.z * ai * iB[j + 2];
        float a3 = v.w * ai * iB[j + 3];
        lsum += a0 * a0 + a1 * a1 + a2 * a2 + a3 * a3;
    }

    __shared__ float red[256];
    red[tid] = lsum;
    __syncthreads();
    for (int s = 128; s > 0; s >>= 1) {
        if (tid < s) red[tid] += red[tid + s];
        __syncthreads();
    }
    if (tid == 0) g_bsum[bx] = w * red[0];
}

__global__ void final_kernel(float* __restrict__ out) {
    __shared__ float red[64];
    float s = (threadIdx.x < BB * NG) ? g_bsum[threadIdx.x] : 0.f;
    red[threadIdx.x] = s;
    __syncthreads();
    for (int st = 32; st > 0; st >>= 1) {
        if (threadIdx.x < st) red[threadIdx.x] += red[threadIdx.x + st];
        __syncthreads();
    }
    if (threadIdx.x == 0)
        out[0] = red[0] / (float)(BB * CC * CC);
}

extern "C" void kernel_launch(void* const* d_in, const int* in_sizes, int n_in,
                              void* d_out, int out_size) {
    const float* fs = (const float*)d_in[0];
    const float* ft = (const float*)d_in[1];
    float* out = (float*)d_out;
    (void)in_sizes; (void)n_in; (void)out_size;

    static bool attr_set = false;
    if (!attr_set) {
        cudaFuncSetAttribute(gram_kernel,
                             cudaFuncAttributeMaxDynamicSharedMemorySize, DYN_SMEM);
        attr_set = true;
    }

    gram_kernel<<<NJOBS, 256, DYN_SMEM>>>(fs, ft);
    reduce_kernel<<<BB * NG, 256>>>();
    final_kernel<<<1, 64>>>(out);
}

// round 4
// speedup vs baseline: 5.7655x; 2.2515x over previous
#include <cuda_runtime.h>
#include <cuda_bf16.h>
#include <cstdint>
#include <math.h>

#define BB 16
#define CC 128
#define TT 16384
#define KSPLIT 16
#define KRANGE (TT / KSPLIT)      // 1024 floats per CTA K-range
#define KT 64                     // K per smem tile (64 bf16 = 128B rows)
#define NKT (KRANGE / KT)         // 16 tiles
#define NG 3
#define NJOBS (BB * NG * KSPLIT)  // 768 CTAs

#define TILE_BYTES 16384          // 128 rows x 64 bf16
#define STAGE_BYTES 32768         // A + B tile
#define DYN_SMEM 65536            // 2 stages

// Scratch (no device allocations allowed -> globals)
__device__ float g_gram[(size_t)KSPLIT * BB * NG * CC * CC];   // 50 MB partials
__device__ float g_inv[2 * BB * CC];                           // [0]=inv_s, [2048]=inv_t
__device__ float g_psum[192];

__device__ __forceinline__ uint32_t smem_u32(const void* p) {
    return (uint32_t)__cvta_generic_to_shared(p);
}
__device__ __forceinline__ uint32_t swz(uint32_t off) {
    return off ^ ((off >> 3) & 0x70);   // SW128
}
__device__ __forceinline__ void ldsm4(uint32_t& r0, uint32_t& r1, uint32_t& r2,
                                      uint32_t& r3, uint32_t addr) {
    asm volatile("ldmatrix.sync.aligned.m8n8.x4.shared.b16 {%0,%1,%2,%3}, [%4];"
                 : "=r"(r0), "=r"(r1), "=r"(r2), "=r"(r3) : "r"(addr));
}
__device__ __forceinline__ void mma16816(float* c, const uint32_t* a,
                                         uint32_t b0, uint32_t b1) {
    asm volatile(
        "mma.sync.aligned.m16n8k16.row.col.f32.bf16.bf16.f32 "
        "{%0,%1,%2,%3}, {%4,%5,%6,%7}, {%8,%9}, {%0,%1,%2,%3};"
        : "+f"(c[0]), "+f"(c[1]), "+f"(c[2]), "+f"(c[3])
        : "r"(a[0]), "r"(a[1]), "r"(a[2]), "r"(a[3]), "r"(b0), "r"(b1));
}
__device__ __forceinline__ uint2 cvt_bf16x4(float4 v) {
    __nv_bfloat162 lo = __floats2bfloat162_rn(v.x, v.y);
    __nv_bfloat162 hi = __floats2bfloat162_rn(v.z, v.w);
    return make_uint2(*(uint32_t*)&lo, *(uint32_t*)&hi);
}

// ---------------------------------------------------------------------------
// Gram kernel: one CTA per (b, gram, ksplit). 256 threads = 8 warps.
// Coalesced loader: lane covers contiguous 16B; 16 lanes = one full 256B row
// segment; warp = 2 rows. Raw float4 prefetch held across MMA loop.
// ---------------------------------------------------------------------------
extern "C" __global__ void __launch_bounds__(256)
gram_kernel(const float* __restrict__ fs, const float* __restrict__ ft) {
    extern __shared__ char smem[];
    const uint32_t smb = smem_u32(smem);

    int bx  = blockIdx.x;
    int b   = bx / (NG * KSPLIT);
    int rem = bx % (NG * KSPLIT);
    int g   = rem / KSPLIT;
    int ks  = rem % KSPLIT;
    bool dual = (g == 2);

    const float* Am = (g == 0) ? ft : fs;
    const float* Bm = (g == 1) ? fs : ft;

    int tid  = threadIdx.x;
    int wid  = tid >> 5;
    int lane = tid & 31;
    int wm   = wid & 3;       // m block: 32*wm
    int wn   = wid >> 2;      // n block: 64*wn
    int gid  = lane >> 2;
    int tid4 = lane & 3;

    // Coalesced loader mapping: lrow0 = tid>>4 (0..15), lcol = tid&15.
    // Row r = lrow0 + i*16 (i=0..7); float4 at column lcol*4.
    int lrow0 = tid >> 4;
    int lcol  = tid & 15;
    const float* baseA = Am + (size_t)b * CC * TT + ks * KRANGE + (size_t)lcol * 4;
    const float* baseB = Bm + (size_t)b * CC * TT + ks * KRANGE + (size_t)lcol * 4;

    // ldmatrix lane addresses
    uint32_t a_row  = (uint32_t)(wm * 32 + (lane & 15));
    uint32_t a_koff = (uint32_t)((lane >> 4) * 16);
    uint32_t b_rowbase = (uint32_t)(wn * 64 + ((lane >> 4) << 3) + (lane & 7));
    uint32_t b_koff = (uint32_t)(((lane >> 3) & 1) * 16);

    float acc[2][8][4];
#pragma unroll
    for (int mi = 0; mi < 2; mi++)
#pragma unroll
        for (int ni = 0; ni < 8; ni++)
#pragma unroll
            for (int q = 0; q < 4; q++) acc[mi][ni][q] = 0.f;

    // ---- prologue: tile 0 ----
    {
#pragma unroll
        for (int i = 0; i < 8; i++) {
            int r = lrow0 + i * 16;
            float4 v = *(const float4*)(baseA + (size_t)r * TT);
            *(uint2*)(smem + swz((uint32_t)r * 128 + lcol * 8)) = cvt_bf16x4(v);
        }
        if (dual) {
#pragma unroll
            for (int i = 0; i < 8; i++) {
                int r = lrow0 + i * 16;
                float4 v = *(const float4*)(baseB + (size_t)r * TT);
                *(uint2*)(smem + TILE_BYTES + swz((uint32_t)r * 128 + lcol * 8)) = cvt_bf16x4(v);
            }
        }
    }
    __syncthreads();

    for (int kt = 0; kt < NKT; kt++) {
        int cur = kt & 1;
        int nxt = cur ^ 1;

        // issue next-tile loads (raw float4, consumed AFTER compute)
        float4 va[8], vb[8];
        if (kt + 1 < NKT) {
            const float* pA = baseA + (size_t)(kt + 1) * KT;
#pragma unroll
            for (int i = 0; i < 8; i++)
                va[i] = *(const float4*)(pA + (size_t)(lrow0 + i * 16) * TT);
            if (dual) {
                const float* pB = baseB + (size_t)(kt + 1) * KT;
#pragma unroll
                for (int i = 0; i < 8; i++)
                    vb[i] = *(const float4*)(pB + (size_t)(lrow0 + i * 16) * TT);
            }
        }

        // compute 4 k16 steps from buffer cur (hides prefetch latency)
        uint32_t abase = smb + cur * STAGE_BYTES;
        uint32_t bbase = abase + (dual ? TILE_BYTES : 0);
#pragma unroll
        for (int kc = 0; kc < 4; kc++) {
            uint32_t kb = (uint32_t)(kc * 32);
            uint32_t afr[2][4];
#pragma unroll
            for (int mi = 0; mi < 2; mi++) {
                uint32_t addr = abase + swz((a_row + mi * 16) * 128 + kb + a_koff);
                ldsm4(afr[mi][0], afr[mi][1], afr[mi][2], afr[mi][3], addr);
            }
#pragma unroll
            for (int nb = 0; nb < 4; nb++) {
                uint32_t r0, r1, r2, r3;
                uint32_t addr = bbase + swz((b_rowbase + nb * 16) * 128 + kb + b_koff);
                ldsm4(r0, r1, r2, r3, addr);
                mma16816(acc[0][2 * nb],     afr[0], r0, r1);
                mma16816(acc[0][2 * nb + 1], afr[0], r2, r3);
                mma16816(acc[1][2 * nb],     afr[1], r0, r1);
                mma16816(acc[1][2 * nb + 1], afr[1], r2, r3);
            }
        }

        // convert + store next tile
        if (kt + 1 < NKT) {
            char* sdst = smem + nxt * STAGE_BYTES;
#pragma unroll
            for (int i = 0; i < 8; i++) {
                uint32_t so = swz((uint32_t)(lrow0 + i * 16) * 128 + lcol * 8);
                *(uint2*)(sdst + so) = cvt_bf16x4(va[i]);
            }
            if (dual) {
#pragma unroll
                for (int i = 0; i < 8; i++) {
                    uint32_t so = swz((uint32_t)(lrow0 + i * 16) * 128 + lcol * 8);
                    *(uint2*)(sdst + TILE_BYTES + so) = cvt_bf16x4(vb[i]);
                }
            }
        }
        __syncthreads();
    }

    // ---- epilogue: partial gram at [i*CC + j] ----
    float* out = g_gram + (((size_t)ks * BB + b) * NG + g) * (CC * CC);
#pragma unroll
    for (int mi = 0; mi < 2; mi++) {
        int r0 = wm * 32 + mi * 16 + gid;
#pragma unroll
        for (int ni = 0; ni < 8; ni++) {
            int c0 = wn * 64 + ni * 8 + tid4 * 2;
            *(float2*)(out + (size_t)r0 * CC + c0) =
                make_float2(acc[mi][ni][0], acc[mi][ni][1]);
            *(float2*)(out + (size_t)(r0 + 8) * CC + c0) =
                make_float2(acc[mi][ni][2], acc[mi][ni][3]);
        }
    }
}

// ---------------------------------------------------------------------------
// Norm kernel: inverse norms from full-K gram diagonals. 32 blocks.
// block n: b = n>>1, which = n&1 (0 -> s from gram g=1, 1 -> t from gram g=0)
// ---------------------------------------------------------------------------
__global__ void norm_kernel() {
    int n = blockIdx.x;
    int b = n >> 1;
    int which = n & 1;
    int gsel = which ? 0 : 1;           // t diag lives in gram g=0, s in g=1
    int d = threadIdx.x;                // 0..127
    if (d >= CC) return;

    const size_t STRIDE = (size_t)BB * NG * CC * CC;
    const float* base = g_gram + ((size_t)b * NG + gsel) * (CC * CC) + (size_t)d * (CC + 1);
    float v = 0.f;
#pragma unroll
    for (int ks = 0; ks < KSPLIT; ks++) v += base[ks * STRIDE];
    g_inv[which * (BB * CC) + b * CC + d] = rsqrtf(fmaxf(v, 1e-24f));
}

// ---------------------------------------------------------------------------
// Reduce kernel: 192 blocks = (b,g) x 4 row-quarters. Coalesced 16KB slices.
// ---------------------------------------------------------------------------
__global__ void reduce_kernel() {
    int blk = blockIdx.x;        // 0..191
    int bg  = blk >> 2;
    int q   = blk & 3;
    int b   = bg / NG;
    int g   = bg % NG;
    int tid = threadIdx.x;

    const float* inv_s = g_inv;
    const float* inv_t = g_inv + BB * CC;
    const float* iA = (g == 0) ? inv_t : inv_s;
    const float* iB = (g == 1) ? inv_s : inv_t;
    float w = (g == 2) ? -2.f : 1.f;

    const size_t STRIDE = (size_t)BB * NG * CC * CC;
    const float* gb = g_gram + ((size_t)b * NG + g) * (CC * CC) + (size_t)q * 32 * CC;

    // 32 rows x 128 cols = 4096 elems = 1024 float4; 256 threads x 4 float4
    float lsum = 0.f;
#pragma unroll
    for (int it = 0; it < 4; it++) {
        int e4 = it * 256 + tid;
        float4 v = make_float4(0.f, 0.f, 0.f, 0.f);
#pragma unroll
        for (int ks = 0; ks < KSPLIT; ks++) {
            float4 u = ((const float4*)(gb + ks * STRIDE))[e4];
            v.x += u.x; v.y += u.y; v.z += u.z; v.w += u.w;
        }
        int e = e4 * 4;
        int i = q * 32 + (e >> 7);
        int j = e & 127;
        float ai = iA[b * CC + i];
        float a0 = v.x * ai * iB[b * CC + j];
        float a1 = v.y * ai * iB[b * CC + j + 1];
        float a2 = v.z * ai * iB[b * CC + j + 2];
        float a3 = v.w * ai * iB[b * CC + j + 3];
        lsum += a0 * a0 + a1 * a1 + a2 * a2 + a3 * a3;
    }

    __shared__ float red[256];
    red[tid] = lsum;
    __syncthreads();
    for (int s = 128; s > 0; s >>= 1) {
        if (tid < s) red[tid] += red[tid + s];
        __syncthreads();
    }
    if (tid == 0) g_psum[blk] = w * red[0];
}

__global__ void final_kernel(float* __restrict__ out) {
    __shared__ float red[256];
    float s = (threadIdx.x < 192) ? g_psum[threadIdx.x] : 0.f;
    red[threadIdx.x] = s;
    __syncthreads();
    for (int st = 128; st > 0; st >>= 1) {
        if (threadIdx.x < st) red[threadIdx.x] += red[threadIdx.x + st];
        __syncthreads();
    }
    if (threadIdx.x == 0)
        out[0] = red[0] / (float)(BB * CC * CC);
}

extern "C" void kernel_launch(void* const* d_in, const int* in_sizes, int n_in,
                              void* d_out, int out_size) {
    const float* fs = (const float*)d_in[0];
    const float* ft = (const float*)d_in[1];
    float* out = (float*)d_out;
    (void)in_sizes; (void)n_in; (void)out_size;

    cudaFuncSetAttribute(gram_kernel,
                         cudaFuncAttributeMaxDynamicSharedMemorySize, DYN_SMEM);

    gram_kernel<<<NJOBS, 256, DYN_SMEM>>>(fs, ft);
    norm_kernel<<<2 * BB, 128>>>();
    reduce_kernel<<<192, 256>>>();
    final_kernel<<<1, 256>>>(out);
}